// round 5
// baseline (speedup 1.0000x reference)
#include <cuda_runtime.h>

// Exact integer reformulation of the PUMA crossbar MVM conv (validated R1-R4):
//   out = RNE_clip( conv_int(xi16, dw) / 4096 ) / 4096
//   xi16 = sext16(rint(x*4096)),  dw = clamp(rint(w*4096), +/-65535)
//
// R5: ci-split for warp parallelism. Block = co-chunk 8 x 2 output rows,
// 256 threads = 16ow x 2cog(4 Cout each) x 2ohsub x 4 ci-quarters, SMEM
// tree reduction of quarters before the RNE epilogue. Grid 512 x 8 warps
// = 4096 warps (vs 1024 in R4), 3 blocks/SM by SMEM (30.7KB).

namespace {
constexpr int CIN = 64, H = 16, W = 16, COUT = 128;
constexpr int L = CIN * 9;            // 576
constexpr int CO_CHUNK = 8;
constexpr int THREADS = 256;
}

__device__ int   g_w[COUT * L];        // quantized weights [co/8][l][co%8]
__device__ short g_x[4 * CIN * H * W]; // quantized inputs, same layout as x

__global__ void prep_kernel(const float* __restrict__ x,
                            const float* __restrict__ w)
{
    int i = blockIdx.x * blockDim.x + threadIdx.x;
    if (i < COUT * L) {
        int co = i / L;
        int l  = i - co * L;
        int q = (int)rintf(w[i] * 4096.0f);      // == wpos - wneg exactly
        q = max(-65535, min(65535, q));
        g_w[(co / CO_CHUNK) * (L * CO_CHUNK) + l * CO_CHUNK + (co % CO_CHUNK)] = q;
    }
    if (i < 4 * CIN * H * W) {
        int xi = (int)rintf(x[i] * 4096.0f);
        g_x[i] = (short)xi;                      // 16-bit two's complement wrap
    }
}

__global__ __launch_bounds__(THREADS, 3)
void conv_mvm_kernel(float* __restrict__ out)
{
    __shared__ int   sw[L * CO_CHUNK];    // 18432 B : [l][co_local(8)]
    __shared__ short sx[CIN * 4 * 18];    //  9216 B : [ci][row 0..3][col -1..16]
    __shared__ int4  red[3 * 64];         //  3072 B : partial sums, quarters 1..3

    const int bid     = blockIdx.x;          // 512 = 16 chunks x 8 ohp x 4 b
    const int coChunk = bid & 15;
    const int ohp     = (bid >> 4) & 7;
    const int b       = bid >> 7;

    const int tid     = threadIdx.x;
    const int ow      = tid & 15;
    const int cog     = (tid >> 4) & 1;      // group of 4 Cout
    const int ohsub   = (tid >> 5) & 1;
    const int quarter = tid >> 6;            // ci quarter 0..3

    // ---- stage weights: linear int4 copy, tile already in [l][co] layout ----
    {
        const int4* src = (const int4*)(g_w + coChunk * (L * CO_CHUNK));
        int4* dst = (int4*)sw;
        for (int idx = tid; idx < (L * CO_CHUNK) / 4; idx += THREADS)
            dst[idx] = src[idx];
    }

    // ---- stage inputs: 64 ci x 4 rows x 18 cols, pre-quantized, zero-pad ----
    for (int idx = tid; idx < CIN * 4 * 18; idx += THREADS) {
        int col = idx % 18;
        int r   = (idx / 18) & 3;
        int ci  = idx / 72;
        int gr  = ohp * 2 - 1 + r;
        int gc  = col - 1;
        short v = 0;
        if ((unsigned)gr < (unsigned)H && (unsigned)gc < (unsigned)W)
            v = g_x[((b * CIN + ci) * H + gr) * W + gc];
        sx[idx] = v;
    }
    __syncthreads();

    // ---- integer MAC mainloop: 16 ci x 9 taps x 4 Cout per thread ----
    int acc0 = 0, acc1 = 0, acc2 = 0, acc3 = 0;
    const int ciBase = quarter * (CIN / 4);
    #pragma unroll 4
    for (int i = 0; i < CIN / 4; ++i) {
        const int ci = ciBase + i;
        const short* xp = &sx[ci * 72 + ohsub * 18 + ow];
        const int*   wp = &sw[ci * 9 * CO_CHUNK + cog * 4];
        #pragma unroll
        for (int ki = 0; ki < 3; ++ki) {
            int x0 = xp[ki * 18 + 0];
            int x1 = xp[ki * 18 + 1];
            int x2 = xp[ki * 18 + 2];
            int4 w0 = *(const int4*)&wp[(ki * 3 + 0) * CO_CHUNK];
            int4 w1 = *(const int4*)&wp[(ki * 3 + 1) * CO_CHUNK];
            int4 w2 = *(const int4*)&wp[(ki * 3 + 2) * CO_CHUNK];
            acc0 += x0 * w0.x + x1 * w1.x + x2 * w2.x;
            acc1 += x0 * w0.y + x1 * w1.y + x2 * w2.y;
            acc2 += x0 * w0.z + x1 * w1.z + x2 * w2.z;
            acc3 += x0 * w0.w + x1 * w1.w + x2 * w2.w;
        }
    }

    // ---- reduce ci-quarters via SMEM ----
    if (quarter != 0)
        red[(quarter - 1) * 64 + (tid & 63)] = make_int4(acc0, acc1, acc2, acc3);
    __syncthreads();
    if (quarter != 0) return;

    #pragma unroll
    for (int q = 0; q < 3; ++q) {
        int4 p = red[q * 64 + tid];
        acc0 += p.x; acc1 += p.y; acc2 += p.z; acc3 += p.w;
    }

    // ---- epilogue: S/2^24 -> RNE to 1/4096 grid, clip int16 ----
    const int oh    = ohp * 2 + ohsub;
    const int coOut = coChunk * CO_CHUNK + cog * 4;
    float* op = out + ((b * COUT + coOut) * H + oh) * W + ow;
    int accs[4] = {acc0, acc1, acc2, acc3};
    #pragma unroll
    for (int j = 0; j < 4; ++j) {
        int S    = accs[j];
        int base = S >> 12;                 // floor(S/4096)
        int rem  = S - (base << 12);        // 0..4095
        if (rem > 2048)       base += 1;
        else if (rem == 2048) base += (base & 1);   // ties to even
        base = max(-32768, min(32767, base));
        op[j * (H * W)] = (float)base * (1.0f / 4096.0f);
    }
}

extern "C" void kernel_launch(void* const* d_in, const int* in_sizes, int n_in,
                              void* d_out, int out_size) {
    const float* x = (const float*)d_in[0];
    const float* w = (const float*)d_in[1];
    // defensive: identify tensors by element count (x: 65536, w: 73728)
    if (n_in >= 2 && in_sizes[0] == 73728 && in_sizes[1] == 65536) {
        x = (const float*)d_in[1];
        w = (const float*)d_in[0];
    }
    prep_kernel<<<(COUT * L + 255) / 256, 256>>>(x, w);
    conv_mvm_kernel<<<512, THREADS>>>((float*)d_out);
}

// round 6
// speedup vs baseline: 1.5287x; 1.5287x over previous
#include <cuda_runtime.h>

// Exact integer reformulation of the PUMA crossbar MVM conv (validated R1-R5):
//   out = RNE_clip( conv_int(xi16, dw) / 4096 ) / 4096
//   xi16 = sext16(rint(x*4096)),  dw = clamp(rint(w*4096), +/-65535)
//
// R6: column-sliding mainloop. Each thread loads only its own input column
// (3 LDS/ci instead of 9) and keeps 12 partial accumulators acc[kj][co4];
// final combine via 2 intra-warp shuffles (pad columns are exactly zero, so
// edge lanes contribute 0 -- exact). 33% fewer LDS, 3x accumulator ILP.
// Grid 256 x 128 threads, co-chunk 16, 4 Cout/thread, single barrier.

namespace {
constexpr int CIN = 64, H = 16, W = 16, COUT = 128;
constexpr int L = CIN * 9;            // 576
constexpr int CO_CHUNK = 16;
constexpr int THREADS = 128;          // 16ow x 4cog x 2ohsub
}

__device__ int   g_w[COUT * L];        // quantized weights [co/16][l][co%16]
__device__ short g_x[4 * CIN * H * W]; // quantized inputs, layout of x

__global__ void prep_kernel(const float* __restrict__ x,
                            const float* __restrict__ w)
{
    int i = blockIdx.x * blockDim.x + threadIdx.x;
    if (i < COUT * L) {
        int co = i / L;
        int l  = i - co * L;
        int q = (int)rintf(w[i] * 4096.0f);      // == wpos - wneg exactly
        q = max(-65535, min(65535, q));
        g_w[(co / CO_CHUNK) * (L * CO_CHUNK) + l * CO_CHUNK + (co % CO_CHUNK)] = q;
    }
    if (i < 4 * CIN * H * W) {
        int xi = (int)rintf(x[i] * 4096.0f);
        g_x[i] = (short)xi;                      // 16-bit two's complement wrap
    }
}

__global__ __launch_bounds__(THREADS, 2)
void conv_mvm_kernel(float* __restrict__ out)
{
    __shared__ int   sw[L * CO_CHUNK];     // 36864 B : [l][co_local(16)]
    __shared__ short sx[CIN * 4 * 16];     //  8192 B : [ci][row 0..3][col 0..15]

    const int bid     = blockIdx.x;          // 256 = 8co x 8ohp x 4b
    const int coChunk = bid & 7;
    const int ohp     = (bid >> 3) & 7;      // output-row pair
    const int b       = bid >> 6;

    const int tid   = threadIdx.x;
    const int ow    = tid & 15;
    const int cog   = (tid >> 4) & 3;        // group of 4 Cout
    const int ohsub = tid >> 6;

    // ---- stage weights: linear int4 copy (prep already tiled [l][co]) ----
    {
        const int4* src = (const int4*)(g_w + coChunk * (L * CO_CHUNK));
        int4* dst = (int4*)sw;
        #pragma unroll
        for (int it = 0; it < (L * CO_CHUNK / 4) / THREADS; ++it)
            dst[it * THREADS + tid] = src[it * THREADS + tid];
    }

    // ---- stage inputs: rows ohp*2-1 .. ohp*2+2, 16 cols, int4 copies ----
    #pragma unroll
    for (int it = 0; it < (CIN * 4 * 2) / THREADS; ++it) {   // 512 int4 total
        int idx = it * THREADS + tid;
        int vec = idx & 1;
        int r   = (idx >> 1) & 3;
        int ci  = idx >> 3;
        int gr  = ohp * 2 - 1 + r;
        int4 v = make_int4(0, 0, 0, 0);
        if ((unsigned)gr < (unsigned)H)
            v = *(const int4*)(g_x + ((b * CIN + ci) * H + gr) * W + vec * 8);
        *((int4*)sx + idx) = v;
    }
    __syncthreads();

    // ---- column-sliding MAC loop: per ci, 3 x-loads, 9 w-loads, 36 IMADs ----
    // acc[kj] accumulates x[row][ow] * w[..][kj]; combined across lanes at end.
    int a00=0,a01=0,a02=0,a03=0;   // kj=0
    int a10=0,a11=0,a12=0,a13=0;   // kj=1
    int a20=0,a21=0,a22=0,a23=0;   // kj=2
    #pragma unroll 4
    for (int ci = 0; ci < CIN; ++ci) {
        const short* xp = &sx[ci * 64 + ohsub * 16 + ow];
        const int*   wp = &sw[ci * 9 * CO_CHUNK + cog * 4];
        #pragma unroll
        for (int ki = 0; ki < 3; ++ki) {
            int xv = xp[ki * 16];                 // x[input row ohsub+ki][ow]
            int4 w0 = *(const int4*)&wp[(ki * 3 + 0) * CO_CHUNK];
            int4 w1 = *(const int4*)&wp[(ki * 3 + 1) * CO_CHUNK];
            int4 w2 = *(const int4*)&wp[(ki * 3 + 2) * CO_CHUNK];
            a00 += xv * w0.x; a01 += xv * w0.y; a02 += xv * w0.z; a03 += xv * w0.w;
            a10 += xv * w1.x; a11 += xv * w1.y; a12 += xv * w1.z; a13 += xv * w1.w;
            a20 += xv * w2.x; a21 += xv * w2.y; a22 += xv * w2.z; a23 += xv * w2.w;
        }
    }

    // ---- lane combine: out[ow] = acc0(ow-1) + acc1(ow) + acc2(ow+1) ----
    // pad columns are zero, so edge lanes contribute exactly 0.
    const unsigned m = 0xFFFFFFFFu;
    int s0, s1, s2, s3;
    {
        int u0 = __shfl_up_sync(m, a00, 1, 16);
        int u1 = __shfl_up_sync(m, a01, 1, 16);
        int u2 = __shfl_up_sync(m, a02, 1, 16);
        int u3 = __shfl_up_sync(m, a03, 1, 16);
        int d0 = __shfl_down_sync(m, a20, 1, 16);
        int d1 = __shfl_down_sync(m, a21, 1, 16);
        int d2 = __shfl_down_sync(m, a22, 1, 16);
        int d3 = __shfl_down_sync(m, a23, 1, 16);
        if (ow == 0)  { u0 = 0; u1 = 0; u2 = 0; u3 = 0; }
        if (ow == 15) { d0 = 0; d1 = 0; d2 = 0; d3 = 0; }
        s0 = u0 + a10 + d0;
        s1 = u1 + a11 + d1;
        s2 = u2 + a12 + d2;
        s3 = u3 + a13 + d3;
    }

    // ---- epilogue: S/2^24 -> RNE to 1/4096 grid, clip int16 ----
    const int oh    = ohp * 2 + ohsub;
    const int coOut = coChunk * CO_CHUNK + cog * 4;
    float* op = out + ((b * COUT + coOut) * H + oh) * W + ow;
    int accs[4] = {s0, s1, s2, s3};
    #pragma unroll
    for (int j = 0; j < 4; ++j) {
        int S    = accs[j];
        int base = S >> 12;                 // floor(S/4096)
        int rem  = S - (base << 12);        // 0..4095
        if (rem > 2048)       base += 1;
        else if (rem == 2048) base += (base & 1);   // ties to even
        base = max(-32768, min(32767, base));
        op[j * (H * W)] = (float)base * (1.0f / 4096.0f);
    }
}

extern "C" void kernel_launch(void* const* d_in, const int* in_sizes, int n_in,
                              void* d_out, int out_size) {
    const float* x = (const float*)d_in[0];
    const float* w = (const float*)d_in[1];
    // defensive: identify tensors by element count (x: 65536, w: 73728)
    if (n_in >= 2 && in_sizes[0] == 73728 && in_sizes[1] == 65536) {
        x = (const float*)d_in[1];
        w = (const float*)d_in[0];
    }
    prep_kernel<<<(COUT * L + 255) / 256, 256>>>(x, w);
    conv_mvm_kernel<<<256, THREADS>>>((float*)d_out);
}